// round 12
// baseline (speedup 1.0000x reference)
#include <cuda_runtime.h>
#include <cuda_fp16.h>
#include <math.h>
#include <stdint.h>

// ---------------- problem constants ----------------
#define NTOT 32768
#define NB   8
#define DIN  64
#define MC   8192
#define KN   32
#define PPC  4096
#define R2   0.04f

// ---------------- fragment-image geometry ----------------
// B images fragment-linear: tile (kt,nt) -> 32 lanes x uint2 {b0,b1}
// (PTX m16n8k16 B layout). fp16 single image (2-pass scheme: (Ah+Al)*Bh).
#define L1_KT 5          // K=80 (67 padded)
#define L2_KT 8          // K=128
#define L3_KT 8          // K=128
#define OFF_L1 0
#define OFF_L2 (OFF_L1 + L1_KT * 16 * 32)
#define OFF_L3 (OFF_L2 + L2_KT * 16 * 32)
#define B_TOTAL (OFF_L3 + L3_KT * 32 * 32)   // uint2 units

// ---------------- scratch ----------------
__device__ int   g_nbr[MC * KN];
__device__ int   g_val[MC * KN];
__device__ uint2 g_B[B_TOTAL];

// A image: per warp [32 rows][256 fp16 cols] = 16KB, swizzled:
//   addr(row, chunk) = warpbase + row*512 + ((chunk ^ (row&7)) * 16)
// hi at chunks 0..15, lo at chunks 16..31.
#define WARP_A_BYTES 16384
#define SMEM_BYTES   (4 * WARP_A_BYTES + 512 * 4)

// ========================= helpers =========================
__device__ __forceinline__ uint32_t smem_u32(const void* p) {
    uint32_t a;
    asm("{ .reg .u64 t; cvta.to.shared.u64 t, %1; cvt.u32.u64 %0, t; }" : "=r"(a) : "l"(p));
    return a;
}
__device__ __forceinline__ void sts32(uint32_t a, uint32_t v) {
    asm volatile("st.shared.b32 [%0], %1;" :: "r"(a), "r"(v));
}
__device__ __forceinline__ void sts128(uint32_t a, uint32_t v0, uint32_t v1, uint32_t v2, uint32_t v3) {
    asm volatile("st.shared.v4.b32 [%0], {%1,%2,%3,%4};" :: "r"(a), "r"(v0), "r"(v1), "r"(v2), "r"(v3));
}
__device__ __forceinline__ void ldsm4(uint32_t* r, uint32_t addr) {
    asm volatile("ldmatrix.sync.aligned.m8n8.x4.shared.b16 {%0,%1,%2,%3}, [%4];"
                 : "=r"(r[0]), "=r"(r[1]), "=r"(r[2]), "=r"(r[3]) : "r"(addr));
}
__device__ __forceinline__ void mma_f16(float* c, const uint32_t* a, uint2 b) {
    asm volatile("mma.sync.aligned.m16n8k16.row.col.f32.f16.f16.f32 "
                 "{%0,%1,%2,%3}, {%4,%5,%6,%7}, {%8,%9}, {%0,%1,%2,%3};"
                 : "+f"(c[0]), "+f"(c[1]), "+f"(c[2]), "+f"(c[3])
                 : "r"(a[0]), "r"(a[1]), "r"(a[2]), "r"(a[3]), "r"(b.x), "r"(b.y));
}
// pack (a,b) -> fp16x2 hi (a in low half) + fp16x2 residual lo
__device__ __forceinline__ void split2(float a, float b, uint32_t& hi, uint32_t& lo) {
    __half2 h = __floats2half2_rn(a, b);          // .x=a (low 16), .y=b (high 16)
    float2 hf = __half22float2(h);
    __half2 l = __floats2half2_rn(a - hf.x, b - hf.y);
    hi = *reinterpret_cast<uint32_t*>(&h);
    lo = *reinterpret_cast<uint32_t*>(&l);
}
__device__ __forceinline__ unsigned int fkey(float f) {
    unsigned int b = __float_as_uint(f);
    return b ^ ((b & 0x80000000u) ? 0xFFFFFFFFu : 0x80000000u);
}

// ============================================================================
// Kernel 0a: zero the fragment image (covers K-padding rows of layer 1)
// ============================================================================
__global__ void zero_w_kernel() {
    uint32_t* p = (uint32_t*)g_B;
    int n = B_TOTAL * 2;
    for (int i = blockIdx.x * blockDim.x + threadIdx.x; i < n; i += gridDim.x * blockDim.x)
        p[i] = 0;
}

// ============================================================================
// Kernel 0b: fp32 weights -> fp16 fragment-linear image (single, rounded)
// ============================================================================
__global__ void conv_w_kernel(const float* __restrict__ W1,
                              const float* __restrict__ W2,
                              const float* __restrict__ W3) {
    int e = blockIdx.x * blockDim.x + threadIdx.x;
    int k, n, NTS; float v; unsigned baseH;
    if (e < 67 * 128) {
        k = e / 128; n = e % 128; v = W1[e]; NTS = 16;
        baseH = OFF_L1 * 4u;
    } else if (e < 67 * 128 + 128 * 128) {
        int i = e - 67 * 128; k = i / 128; n = i % 128; v = W2[i]; NTS = 16;
        baseH = OFF_L2 * 4u;
    } else if (e < 67 * 128 + 128 * 128 + 128 * 256) {
        int i = e - 67 * 128 - 128 * 128; k = i / 256; n = i % 256; v = W3[i]; NTS = 32;
        baseH = OFF_L3 * 4u;
    } else return;

    __half hb = __float2half_rn(v);

    int kt = k >> 4, kin = k & 15, nt = n >> 3, nin = n & 7;
    int lane = nin * 4 + ((kin & 7) >> 1);
    int reg  = kin >> 3;
    int half = kin & 1;
    unsigned idx = ((unsigned)(kt * NTS + nt) * 32 + lane) * 4 + reg * 2 + half;
    unsigned short* B = (unsigned short*)g_B;
    B[baseH + idx] = __half_as_ushort(hb);
}

// ============================================================================
// Kernel 1: ball-filtered exact KNN with parallel rank selection.
// ============================================================================
#define CANDCAP 2048
__global__ __launch_bounds__(256) void knn_kernel(
    const float* __restrict__ pos,
    const int*   __restrict__ batch,
    const int*   __restrict__ idx)
{
    __shared__ unsigned long long cand[CANDCAP];
    __shared__ int  woff[9];
    __shared__ float sc[4];
    __shared__ int   sbase;

    const int m    = blockIdx.x;
    const int tid  = threadIdx.x;
    const int lane = tid & 31, w = tid >> 5;

    if (tid == 0) {
        int ci = idx[m];
        float cx = pos[3 * ci], cy = pos[3 * ci + 1], cz = pos[3 * ci + 2];
        sc[0] = cx; sc[1] = cy; sc[2] = cz;
        sc[3] = cx * cx + cy * cy + cz * cz;
        sbase = batch[ci] * PPC;
    }
    __syncthreads();

    const float cx = sc[0], cy = sc[1], cz = sc[2], cc = sc[3];
    const int base = sbase;

    float d2r[PPC / 256];
    int cnt = 0;
    #pragma unroll
    for (int r = 0; r < PPC / 256; r++) {
        int j = tid + r * 256;
        const float* p = pos + 3 * (base + j);
        float px = p[0], py = p[1], pz = p[2];
        float pp  = px * px + py * py + pz * pz;
        float dot = cx * px + cy * py + cz * pz;
        float d2  = (cc + pp) - 2.0f * dot;
        d2r[r] = d2;
        cnt += (d2 <= R2) ? 1 : 0;
    }
    #pragma unroll
    for (int off = 16; off; off >>= 1) cnt += __shfl_down_sync(0xffffffffu, cnt, off);
    if (lane == 0) woff[w] = cnt;
    __syncthreads();
    if (tid == 0) {
        int acc = 0;
        #pragma unroll
        for (int t = 0; t < 8; t++) { int c = woff[t]; woff[t] = acc; acc += c; }
        woff[8] = acc;
    }
    __syncthreads();

    {
        int off = woff[w];
        #pragma unroll
        for (int r = 0; r < PPC / 256; r++) {
            int j = tid + r * 256;
            bool pred = (d2r[r] <= R2);
            unsigned int mask = __ballot_sync(0xffffffffu, pred);
            if (pred) {
                int p = off + __popc(mask & ((1u << lane) - 1u));
                if (p < CANDCAP)
                    cand[p] = ((unsigned long long)fkey(d2r[r]) << 12) | (unsigned)j;
            }
            off += __popc(mask);
        }
    }
    __syncthreads();

    const int C = min(woff[8], CANDCAP);
    for (int s = tid; s < C; s += 256) {
        unsigned long long key = cand[s];
        int rank = 0;
        for (int t = 0; t < C; t++) rank += (cand[t] < key) ? 1 : 0;
        if (rank < KN) {
            g_nbr[m * KN + rank] = base + (int)(key & 0xFFFu);
            g_val[m * KN + rank] = 1;
        }
    }
    if (tid >= C && tid < KN) {
        g_nbr[m * KN + tid] = base;
        g_val[m * KN + tid] = 0;
    }
}

// ============================================================================
// Warp-level GEMM:  acc += (Ah + Al) * Bh     (fp16 2-pass)
// ============================================================================
template <int KT, int NT, int NTS>
__device__ __forceinline__ void gemm_acc(uint32_t abase,
                                         const uint2* __restrict__ Bh,
                                         int ntoff, int lane,
                                         float (&acc)[2][16][4])
{
    #pragma unroll
    for (int m = 0; m < 2; m++)
        #pragma unroll
        for (int nt = 0; nt < NT; nt++)
            #pragma unroll
            for (int q = 0; q < 4; q++) acc[m][nt][q] = 0.0f;

    const int i = lane >> 3, jj = lane & 7;
    const int cpart = i >> 1;
    const uint32_t rb0 = abase + (uint32_t)(jj + (i & 1) * 8) * 512;
    const uint32_t rb1 = rb0 + 16 * 512;

    for (int kt = 0; kt < KT; kt++) {
        uint32_t ch = (uint32_t)((kt * 2 + cpart) ^ jj) << 4;
        uint32_t ah0[4], ah1[4], al0[4], al1[4];
        ldsm4(ah0, rb0 + ch);
        ldsm4(ah1, rb1 + ch);
        ldsm4(al0, rb0 + ch + 256);
        ldsm4(al1, rb1 + ch + 256);
        const uint2* bph = Bh + (size_t)(kt * NTS + ntoff) * 32 + lane;
        #pragma unroll
        for (int nt = 0; nt < NT; nt++) {
            uint2 bh = __ldg(bph + nt * 32);
            mma_f16(acc[0][nt], ah0, bh);
            mma_f16(acc[1][nt], ah1, bh);
            mma_f16(acc[0][nt], al0, bh);
            mma_f16(acc[1][nt], al1, bh);
        }
    }
}

// mid-layer epilogue: bias + relu + fp16 hi/lo split -> back into A image
__device__ __forceinline__ void epi_mid(float (&acc)[2][16][4],
                                        const float* __restrict__ bias,
                                        uint32_t abase, int lane)
{
    const int grp = lane >> 2, tig = lane & 3;
    #pragma unroll
    for (int nt = 0; nt < 16; nt++) {
        float b0 = bias[nt * 8 + tig * 2];
        float b1 = bias[nt * 8 + tig * 2 + 1];
        #pragma unroll
        for (int m = 0; m < 2; m++) {
            int row0 = m * 16 + grp, row1 = row0 + 8;
            float v0 = fmaxf(acc[m][nt][0] + b0, 0.0f);
            float v1 = fmaxf(acc[m][nt][1] + b1, 0.0f);
            float v2 = fmaxf(acc[m][nt][2] + b0, 0.0f);
            float v3 = fmaxf(acc[m][nt][3] + b1, 0.0f);
            uint32_t h0, l0, h1, l1;
            split2(v0, v1, h0, l0);
            split2(v2, v3, h1, l1);
            uint32_t r0b = abase + row0 * 512, r1b = abase + row1 * 512;
            sts32(r0b + ((uint32_t)(nt ^ (row0 & 7)) << 4) + tig * 4, h0);
            sts32(r0b + ((uint32_t)((16 + nt) ^ (row0 & 7)) << 4) + tig * 4, l0);
            sts32(r1b + ((uint32_t)(nt ^ (row1 & 7)) << 4) + tig * 4, h1);
            sts32(r1b + ((uint32_t)((16 + nt) ^ (row1 & 7)) << 4) + tig * 4, l1);
        }
    }
}

// final epilogue: bias + relu + masked max over 32 edges, write 128 cols
__device__ __forceinline__ void epi_out(float (&acc)[2][16][4],
                                        const float* __restrict__ bias,
                                        unsigned vmask, float* __restrict__ outp,
                                        int lane)
{
    const int grp = lane >> 2, tig = lane & 3;
    #pragma unroll
    for (int nt = 0; nt < 16; nt++) {
        float b0 = bias[nt * 8 + tig * 2];
        float b1 = bias[nt * 8 + tig * 2 + 1];
        float p0 = 0.0f, p1 = 0.0f;
        #pragma unroll
        for (int m = 0; m < 2; m++) {
            int r0 = m * 16 + grp, r1 = r0 + 8;
            bool k0 = (vmask >> r0) & 1, k1 = (vmask >> r1) & 1;
            float v0 = k0 ? fmaxf(acc[m][nt][0] + b0, 0.0f) : 0.0f;
            float v1 = k0 ? fmaxf(acc[m][nt][1] + b1, 0.0f) : 0.0f;
            float v2 = k1 ? fmaxf(acc[m][nt][2] + b0, 0.0f) : 0.0f;
            float v3 = k1 ? fmaxf(acc[m][nt][3] + b1, 0.0f) : 0.0f;
            p0 = fmaxf(p0, fmaxf(v0, v2));
            p1 = fmaxf(p1, fmaxf(v1, v3));
        }
        #pragma unroll
        for (int off = 4; off <= 16; off <<= 1) {
            p0 = fmaxf(p0, __shfl_xor_sync(0xffffffffu, p0, off));
            p1 = fmaxf(p1, __shfl_xor_sync(0xffffffffu, p1, off));
        }
        if (grp == 0)
            *(float2*)(outp + nt * 8 + tig * 2) = make_float2(p0, p1);
    }
}

// ============================================================================
// Kernel 2: warp-per-center fused MLP on mma.sync tensor cores.
// ============================================================================
__global__ __launch_bounds__(128, 3) void mlp_kernel(
    const float* __restrict__ x,   const float* __restrict__ pos,
    const int*   __restrict__ batch, const int* __restrict__ idx,
    const float* __restrict__ b1, const float* __restrict__ b2,
    const float* __restrict__ b3, float* __restrict__ out)
{
    extern __shared__ __align__(16) unsigned char smem[];
    float* biasSh = (float*)(smem + 4 * WARP_A_BYTES);

    const int tid = threadIdx.x;
    const int lane = tid & 31, w = tid >> 5;
    const int c = blockIdx.x * 4 + w;

    for (int i = tid; i < 512; i += 128) {
        float bv = (i < 128) ? __ldg(b1 + i) : (i < 256) ? __ldg(b2 + i - 128) : __ldg(b3 + i - 256);
        biasSh[i] = bv;
    }
    __syncthreads();

    const uint32_t abase = smem_u32(smem) + (uint32_t)w * WARP_A_BYTES;

    // ---- per-lane edge
    const int nb  = __ldg((const int*)g_nbr + c * KN + lane);
    const int vld = __ldg((const int*)g_val + c * KN + lane);
    const int ci  = __ldg(idx + c);
    const float cpx = __ldg(pos + 3 * ci), cpy = __ldg(pos + 3 * ci + 1), cpz = __ldg(pos + 3 * ci + 2);
    const unsigned vmask = __ballot_sync(0xffffffffu, vld);

    // ---- gather row = lane into A image (hi chunks 0..9, lo chunks 16..25)
    {
        const uint32_t rowbase = abase + (uint32_t)lane * 512;
        const int r7 = lane & 7;
        const float4* xr = (const float4*)(x + (size_t)nb * DIN);
        #pragma unroll
        for (int q = 0; q < 16; q++) {
            float4 v = __ldg(xr + q);
            uint32_t h0, l0, h1, l1;
            split2(v.x, v.y, h0, l0);
            split2(v.z, v.w, h1, l1);
            uint32_t bo = ((uint32_t)(q & 1)) << 3;
            uint32_t chH = ((uint32_t)((q >> 1) ^ r7)) << 4;
            uint32_t chL = ((uint32_t)((16 + (q >> 1)) ^ r7)) << 4;
            sts32(rowbase + chH + bo, h0);
            sts32(rowbase + chH + bo + 4, h1);
            sts32(rowbase + chL + bo, l0);
            sts32(rowbase + chL + bo + 4, l1);
        }
        float rx = __ldg(pos + 3 * nb)     - cpx;
        float ry = __ldg(pos + 3 * nb + 1) - cpy;
        float rz = __ldg(pos + 3 * nb + 2) - cpz;
        uint32_t hA, lA, hB, lB;
        split2(rx, ry, hA, lA);
        split2(rz, 0.0f, hB, lB);
        sts128(rowbase + ((uint32_t)(8 ^ r7) << 4), hA, hB, 0u, 0u);       // cols 64..71 hi
        sts128(rowbase + ((uint32_t)(9 ^ r7) << 4), 0u, 0u, 0u, 0u);       // cols 72..79 hi
        sts128(rowbase + ((uint32_t)(24 ^ r7) << 4), lA, lB, 0u, 0u);      // cols 64..71 lo
        sts128(rowbase + ((uint32_t)(25 ^ r7) << 4), 0u, 0u, 0u, 0u);      // cols 72..79 lo
    }
    __syncwarp();

    float acc[2][16][4];

    // layer 1: K=80 -> 128
    gemm_acc<L1_KT, 16, 16>(abase, g_B + OFF_L1, 0, lane, acc);
    __syncwarp();
    epi_mid(acc, biasSh, abase, lane);
    __syncwarp();

    // layer 2: 128 -> 128
    gemm_acc<L2_KT, 16, 16>(abase, g_B + OFF_L2, 0, lane, acc);
    __syncwarp();
    epi_mid(acc, biasSh + 128, abase, lane);
    __syncwarp();

    // layer 3: 128 -> 256 in two 128-col chunks, fused masked max
    gemm_acc<L3_KT, 16, 32>(abase, g_B + OFF_L3, 0, lane, acc);
    epi_out(acc, biasSh + 256, vmask, out + (size_t)c * 256, lane);
    gemm_acc<L3_KT, 16, 32>(abase, g_B + OFF_L3, 16, lane, acc);
    epi_out(acc, biasSh + 384, vmask, out + (size_t)c * 256 + 128, lane);

    // tails: pos[idx] then batch[idx]
    if (lane == 0) out[(size_t)MC * 256 + (size_t)c * 3 + 0] = cpx;
    if (lane == 1) out[(size_t)MC * 256 + (size_t)c * 3 + 1] = cpy;
    if (lane == 2) out[(size_t)MC * 256 + (size_t)c * 3 + 2] = cpz;
    if (lane == 3) out[(size_t)MC * 259 + c] = (float)__ldg(batch + ci);
}

// ============================================================================
extern "C" void kernel_launch(void* const* d_in, const int* in_sizes, int n_in,
                              void* d_out, int out_size)
{
    const float* x     = (const float*)d_in[0];
    const float* pos   = (const float*)d_in[1];
    const int*   batch = (const int*)  d_in[2];
    const int*   idx   = (const int*)  d_in[3];
    const float* W1    = (const float*)d_in[4];
    const float* b1    = (const float*)d_in[5];
    const float* W2    = (const float*)d_in[6];
    const float* b2    = (const float*)d_in[7];
    const float* W3    = (const float*)d_in[8];
    const float* b3    = (const float*)d_in[9];
    float* out = (float*)d_out;

    cudaFuncSetAttribute(mlp_kernel, cudaFuncAttributeMaxDynamicSharedMemorySize, SMEM_BYTES);

    zero_w_kernel<<<64, 256>>>();
    conv_w_kernel<<<(67 * 128 + 128 * 128 + 128 * 256 + 255) / 256, 256>>>(W1, W2, W3);
    knn_kernel<<<MC, 256>>>(pos, batch, idx);
    mlp_kernel<<<MC / 4, 128, SMEM_BYTES>>>(x, pos, batch, idx, b1, b2, b3, out);
}

// round 13
// speedup vs baseline: 1.6748x; 1.6748x over previous
#include <cuda_runtime.h>
#include <cuda_fp16.h>
#include <math.h>
#include <stdint.h>

// ---------------- problem constants ----------------
#define NTOT 32768
#define NB   8
#define DIN  64
#define MC   8192
#define KN   32
#define PPC  4096
#define R2   0.04f

// ---------------- fragment-image geometry ----------------
// B images fragment-linear: tile (kt,nt) -> 32 lanes x uint2 {b0,b1}
// (PTX m16n8k16 B layout). fp16 single image (2-pass scheme: (Ah+Al)*Bh).
#define L1_KT 5          // K=80 (67 padded)
#define L2_KT 8          // K=128
#define L3_KT 8          // K=128
#define OFF_L1 0
#define OFF_L2 (OFF_L1 + L1_KT * 16 * 32)
#define OFF_L3 (OFF_L2 + L2_KT * 16 * 32)
#define B_TOTAL (OFF_L3 + L3_KT * 32 * 32)   // uint2 units

// ---------------- scratch ----------------
__device__ int   g_nbr[MC * KN];
__device__ int   g_val[MC * KN];
__device__ uint2 g_B[B_TOTAL];

// A image: per warp [32 rows][256 fp16 cols] = 16KB, swizzled:
//   addr(row, chunk) = warpbase + row*512 + ((chunk ^ (row&7)) * 16)
// hi at chunks 0..15, lo at chunks 16..31.
#define WARP_A_BYTES 16384
#define SMEM_BYTES   (4 * WARP_A_BYTES + 512 * 4)

// ========================= helpers =========================
__device__ __forceinline__ uint32_t smem_u32(const void* p) {
    uint32_t a;
    asm("{ .reg .u64 t; cvta.to.shared.u64 t, %1; cvt.u32.u64 %0, t; }" : "=r"(a) : "l"(p));
    return a;
}
__device__ __forceinline__ void sts32(uint32_t a, uint32_t v) {
    asm volatile("st.shared.b32 [%0], %1;" :: "r"(a), "r"(v));
}
__device__ __forceinline__ void sts128(uint32_t a, uint32_t v0, uint32_t v1, uint32_t v2, uint32_t v3) {
    asm volatile("st.shared.v4.b32 [%0], {%1,%2,%3,%4};" :: "r"(a), "r"(v0), "r"(v1), "r"(v2), "r"(v3));
}
__device__ __forceinline__ void ldsm4(uint32_t* r, uint32_t addr) {
    asm volatile("ldmatrix.sync.aligned.m8n8.x4.shared.b16 {%0,%1,%2,%3}, [%4];"
                 : "=r"(r[0]), "=r"(r[1]), "=r"(r[2]), "=r"(r[3]) : "r"(addr));
}
__device__ __forceinline__ void mma_f16(float* c, const uint32_t* a, uint2 b) {
    asm volatile("mma.sync.aligned.m16n8k16.row.col.f32.f16.f16.f32 "
                 "{%0,%1,%2,%3}, {%4,%5,%6,%7}, {%8,%9}, {%0,%1,%2,%3};"
                 : "+f"(c[0]), "+f"(c[1]), "+f"(c[2]), "+f"(c[3])
                 : "r"(a[0]), "r"(a[1]), "r"(a[2]), "r"(a[3]), "r"(b.x), "r"(b.y));
}
// pack (a,b) -> fp16x2 hi (a in low half) + fp16x2 residual lo
__device__ __forceinline__ void split2(float a, float b, uint32_t& hi, uint32_t& lo) {
    __half2 h = __floats2half2_rn(a, b);          // .x=a (low 16), .y=b (high 16)
    float2 hf = __half22float2(h);
    __half2 l = __floats2half2_rn(a - hf.x, b - hf.y);
    hi = *reinterpret_cast<uint32_t*>(&h);
    lo = *reinterpret_cast<uint32_t*>(&l);
}
__device__ __forceinline__ unsigned int fkey(float f) {
    unsigned int b = __float_as_uint(f);
    return b ^ ((b & 0x80000000u) ? 0xFFFFFFFFu : 0x80000000u);
}

// ============================================================================
// Kernel 0a: zero the fragment image (covers K-padding rows of layer 1)
// ============================================================================
__global__ void zero_w_kernel() {
    uint32_t* p = (uint32_t*)g_B;
    int n = B_TOTAL * 2;
    for (int i = blockIdx.x * blockDim.x + threadIdx.x; i < n; i += gridDim.x * blockDim.x)
        p[i] = 0;
}

// ============================================================================
// Kernel 0b: fp32 weights -> fp16 fragment-linear image (single, rounded)
// ============================================================================
__global__ void conv_w_kernel(const float* __restrict__ W1,
                              const float* __restrict__ W2,
                              const float* __restrict__ W3) {
    int e = blockIdx.x * blockDim.x + threadIdx.x;
    int k, n, NTS; float v; unsigned baseH;
    if (e < 67 * 128) {
        k = e / 128; n = e % 128; v = W1[e]; NTS = 16;
        baseH = OFF_L1 * 4u;
    } else if (e < 67 * 128 + 128 * 128) {
        int i = e - 67 * 128; k = i / 128; n = i % 128; v = W2[i]; NTS = 16;
        baseH = OFF_L2 * 4u;
    } else if (e < 67 * 128 + 128 * 128 + 128 * 256) {
        int i = e - 67 * 128 - 128 * 128; k = i / 256; n = i % 256; v = W3[i]; NTS = 32;
        baseH = OFF_L3 * 4u;
    } else return;

    __half hb = __float2half_rn(v);

    int kt = k >> 4, kin = k & 15, nt = n >> 3, nin = n & 7;
    int lane = nin * 4 + ((kin & 7) >> 1);
    int reg  = kin >> 3;
    int half = kin & 1;
    unsigned idx = ((unsigned)(kt * NTS + nt) * 32 + lane) * 4 + reg * 2 + half;
    unsigned short* B = (unsigned short*)g_B;
    B[baseH + idx] = __half_as_ushort(hb);
}

// ============================================================================
// Kernel 1: ball-filtered exact KNN with parallel rank selection.
// ============================================================================
#define CANDCAP 2048
__global__ __launch_bounds__(256) void knn_kernel(
    const float* __restrict__ pos,
    const int*   __restrict__ batch,
    const int*   __restrict__ idx)
{
    __shared__ unsigned long long cand[CANDCAP];
    __shared__ int  woff[9];
    __shared__ float sc[4];
    __shared__ int   sbase;

    const int m    = blockIdx.x;
    const int tid  = threadIdx.x;
    const int lane = tid & 31, w = tid >> 5;

    if (tid == 0) {
        int ci = idx[m];
        float cx = pos[3 * ci], cy = pos[3 * ci + 1], cz = pos[3 * ci + 2];
        sc[0] = cx; sc[1] = cy; sc[2] = cz;
        sc[3] = cx * cx + cy * cy + cz * cz;
        sbase = batch[ci] * PPC;
    }
    __syncthreads();

    const float cx = sc[0], cy = sc[1], cz = sc[2], cc = sc[3];
    const int base = sbase;

    float d2r[PPC / 256];
    int cnt = 0;
    #pragma unroll
    for (int r = 0; r < PPC / 256; r++) {
        int j = tid + r * 256;
        const float* p = pos + 3 * (base + j);
        float px = p[0], py = p[1], pz = p[2];
        float pp  = px * px + py * py + pz * pz;
        float dot = cx * px + cy * py + cz * pz;
        float d2  = (cc + pp) - 2.0f * dot;
        d2r[r] = d2;
        cnt += (d2 <= R2) ? 1 : 0;
    }
    #pragma unroll
    for (int off = 16; off; off >>= 1) cnt += __shfl_down_sync(0xffffffffu, cnt, off);
    if (lane == 0) woff[w] = cnt;
    __syncthreads();
    if (tid == 0) {
        int acc = 0;
        #pragma unroll
        for (int t = 0; t < 8; t++) { int c = woff[t]; woff[t] = acc; acc += c; }
        woff[8] = acc;
    }
    __syncthreads();

    {
        int off = woff[w];
        #pragma unroll
        for (int r = 0; r < PPC / 256; r++) {
            int j = tid + r * 256;
            bool pred = (d2r[r] <= R2);
            unsigned int mask = __ballot_sync(0xffffffffu, pred);
            if (pred) {
                int p = off + __popc(mask & ((1u << lane) - 1u));
                if (p < CANDCAP)
                    cand[p] = ((unsigned long long)fkey(d2r[r]) << 12) | (unsigned)j;
            }
            off += __popc(mask);
        }
    }
    __syncthreads();

    const int C = min(woff[8], CANDCAP);
    for (int s = tid; s < C; s += 256) {
        unsigned long long key = cand[s];
        int rank = 0;
        for (int t = 0; t < C; t++) rank += (cand[t] < key) ? 1 : 0;
        if (rank < KN) {
            g_nbr[m * KN + rank] = base + (int)(key & 0xFFFu);
            g_val[m * KN + rank] = 1;
        }
    }
    if (tid >= C && tid < KN) {
        g_nbr[m * KN + tid] = base;
        g_val[m * KN + tid] = 0;
    }
}

// ============================================================================
// Warp-level GEMM:  acc += (Ah + Al) * Bh     (fp16 2-pass)
// All 16 B fragments of a k-tile are batched into registers BEFORE the MMA
// burst: 16 independent LDG.64 in flight -> L2 latency amortized over 64 MMAs.
// ============================================================================
template <int KT, int NT, int NTS>
__device__ __forceinline__ void gemm_acc(uint32_t abase,
                                         const uint2* __restrict__ Bh,
                                         int ntoff, int lane,
                                         float (&acc)[2][16][4])
{
    #pragma unroll
    for (int m = 0; m < 2; m++)
        #pragma unroll
        for (int nt = 0; nt < NT; nt++)
            #pragma unroll
            for (int q = 0; q < 4; q++) acc[m][nt][q] = 0.0f;

    const int i = lane >> 3, jj = lane & 7;
    const int cpart = i >> 1;
    const uint32_t rb0 = abase + (uint32_t)(jj + (i & 1) * 8) * 512;
    const uint32_t rb1 = rb0 + 16 * 512;

    for (int kt = 0; kt < KT; kt++) {
        // batch all B fragments for this k-tile
        uint2 bfr[NT];
        const uint2* bph = Bh + (size_t)(kt * NTS + ntoff) * 32 + lane;
        #pragma unroll
        for (int nt = 0; nt < NT; nt++) bfr[nt] = __ldg(bph + nt * 32);

        uint32_t ch = (uint32_t)((kt * 2 + cpart) ^ jj) << 4;
        uint32_t ah0[4], ah1[4], al0[4], al1[4];
        ldsm4(ah0, rb0 + ch);
        ldsm4(ah1, rb1 + ch);
        ldsm4(al0, rb0 + ch + 256);
        ldsm4(al1, rb1 + ch + 256);

        #pragma unroll
        for (int nt = 0; nt < NT; nt++) {
            mma_f16(acc[0][nt], ah0, bfr[nt]);
            mma_f16(acc[1][nt], ah1, bfr[nt]);
            mma_f16(acc[0][nt], al0, bfr[nt]);
            mma_f16(acc[1][nt], al1, bfr[nt]);
        }
    }
}

// mid-layer epilogue: bias + relu + fp16 hi/lo split -> back into A image
__device__ __forceinline__ void epi_mid(float (&acc)[2][16][4],
                                        const float* __restrict__ bias,
                                        uint32_t abase, int lane)
{
    const int grp = lane >> 2, tig = lane & 3;
    #pragma unroll
    for (int nt = 0; nt < 16; nt++) {
        float b0 = bias[nt * 8 + tig * 2];
        float b1 = bias[nt * 8 + tig * 2 + 1];
        #pragma unroll
        for (int m = 0; m < 2; m++) {
            int row0 = m * 16 + grp, row1 = row0 + 8;
            float v0 = fmaxf(acc[m][nt][0] + b0, 0.0f);
            float v1 = fmaxf(acc[m][nt][1] + b1, 0.0f);
            float v2 = fmaxf(acc[m][nt][2] + b0, 0.0f);
            float v3 = fmaxf(acc[m][nt][3] + b1, 0.0f);
            uint32_t h0, l0, h1, l1;
            split2(v0, v1, h0, l0);
            split2(v2, v3, h1, l1);
            uint32_t r0b = abase + row0 * 512, r1b = abase + row1 * 512;
            sts32(r0b + ((uint32_t)(nt ^ (row0 & 7)) << 4) + tig * 4, h0);
            sts32(r0b + ((uint32_t)((16 + nt) ^ (row0 & 7)) << 4) + tig * 4, l0);
            sts32(r1b + ((uint32_t)(nt ^ (row1 & 7)) << 4) + tig * 4, h1);
            sts32(r1b + ((uint32_t)((16 + nt) ^ (row1 & 7)) << 4) + tig * 4, l1);
        }
    }
}

// final epilogue: bias + relu + masked max over 32 edges, write 128 cols
__device__ __forceinline__ void epi_out(float (&acc)[2][16][4],
                                        const float* __restrict__ bias,
                                        unsigned vmask, float* __restrict__ outp,
                                        int lane)
{
    const int grp = lane >> 2, tig = lane & 3;
    #pragma unroll
    for (int nt = 0; nt < 16; nt++) {
        float b0 = bias[nt * 8 + tig * 2];
        float b1 = bias[nt * 8 + tig * 2 + 1];
        float p0 = 0.0f, p1 = 0.0f;
        #pragma unroll
        for (int m = 0; m < 2; m++) {
            int r0 = m * 16 + grp, r1 = r0 + 8;
            bool k0 = (vmask >> r0) & 1, k1 = (vmask >> r1) & 1;
            float v0 = k0 ? fmaxf(acc[m][nt][0] + b0, 0.0f) : 0.0f;
            float v1 = k0 ? fmaxf(acc[m][nt][1] + b1, 0.0f) : 0.0f;
            float v2 = k1 ? fmaxf(acc[m][nt][2] + b0, 0.0f) : 0.0f;
            float v3 = k1 ? fmaxf(acc[m][nt][3] + b1, 0.0f) : 0.0f;
            p0 = fmaxf(p0, fmaxf(v0, v2));
            p1 = fmaxf(p1, fmaxf(v1, v3));
        }
        #pragma unroll
        for (int off = 4; off <= 16; off <<= 1) {
            p0 = fmaxf(p0, __shfl_xor_sync(0xffffffffu, p0, off));
            p1 = fmaxf(p1, __shfl_xor_sync(0xffffffffu, p1, off));
        }
        if (grp == 0)
            *(float2*)(outp + nt * 8 + tig * 2) = make_float2(p0, p1);
    }
}

// ============================================================================
// Kernel 2: warp-per-center fused MLP on mma.sync tensor cores.
// No min-blocks cap: full register budget (2 CTAs/SM) so B-fragment LDG
// batches stay in flight.
// ============================================================================
__global__ __launch_bounds__(128) void mlp_kernel(
    const float* __restrict__ x,   const float* __restrict__ pos,
    const int*   __restrict__ batch, const int* __restrict__ idx,
    const float* __restrict__ b1, const float* __restrict__ b2,
    const float* __restrict__ b3, float* __restrict__ out)
{
    extern __shared__ __align__(16) unsigned char smem[];
    float* biasSh = (float*)(smem + 4 * WARP_A_BYTES);

    const int tid = threadIdx.x;
    const int lane = tid & 31, w = tid >> 5;
    const int c = blockIdx.x * 4 + w;

    for (int i = tid; i < 512; i += 128) {
        float bv = (i < 128) ? __ldg(b1 + i) : (i < 256) ? __ldg(b2 + i - 128) : __ldg(b3 + i - 256);
        biasSh[i] = bv;
    }
    __syncthreads();

    const uint32_t abase = smem_u32(smem) + (uint32_t)w * WARP_A_BYTES;

    // ---- per-lane edge
    const int nb  = __ldg((const int*)g_nbr + c * KN + lane);
    const int vld = __ldg((const int*)g_val + c * KN + lane);
    const int ci  = __ldg(idx + c);
    const float cpx = __ldg(pos + 3 * ci), cpy = __ldg(pos + 3 * ci + 1), cpz = __ldg(pos + 3 * ci + 2);
    const unsigned vmask = __ballot_sync(0xffffffffu, vld);

    // ---- gather row = lane into A image (hi chunks 0..9, lo chunks 16..25)
    {
        const uint32_t rowbase = abase + (uint32_t)lane * 512;
        const int r7 = lane & 7;
        const float4* xr = (const float4*)(x + (size_t)nb * DIN);
        #pragma unroll
        for (int q = 0; q < 16; q++) {
            float4 v = __ldg(xr + q);
            uint32_t h0, l0, h1, l1;
            split2(v.x, v.y, h0, l0);
            split2(v.z, v.w, h1, l1);
            uint32_t bo = ((uint32_t)(q & 1)) << 3;
            uint32_t chH = ((uint32_t)((q >> 1) ^ r7)) << 4;
            uint32_t chL = ((uint32_t)((16 + (q >> 1)) ^ r7)) << 4;
            sts32(rowbase + chH + bo, h0);
            sts32(rowbase + chH + bo + 4, h1);
            sts32(rowbase + chL + bo, l0);
            sts32(rowbase + chL + bo + 4, l1);
        }
        float rx = __ldg(pos + 3 * nb)     - cpx;
        float ry = __ldg(pos + 3 * nb + 1) - cpy;
        float rz = __ldg(pos + 3 * nb + 2) - cpz;
        uint32_t hA, lA, hB, lB;
        split2(rx, ry, hA, lA);
        split2(rz, 0.0f, hB, lB);
        sts128(rowbase + ((uint32_t)(8 ^ r7) << 4), hA, hB, 0u, 0u);       // cols 64..71 hi
        sts128(rowbase + ((uint32_t)(9 ^ r7) << 4), 0u, 0u, 0u, 0u);       // cols 72..79 hi
        sts128(rowbase + ((uint32_t)(24 ^ r7) << 4), lA, lB, 0u, 0u);      // cols 64..71 lo
        sts128(rowbase + ((uint32_t)(25 ^ r7) << 4), 0u, 0u, 0u, 0u);      // cols 72..79 lo
    }
    __syncwarp();

    float acc[2][16][4];

    // layer 1: K=80 -> 128
    gemm_acc<L1_KT, 16, 16>(abase, g_B + OFF_L1, 0, lane, acc);
    __syncwarp();
    epi_mid(acc, biasSh, abase, lane);
    __syncwarp();

    // layer 2: 128 -> 128
    gemm_acc<L2_KT, 16, 16>(abase, g_B + OFF_L2, 0, lane, acc);
    __syncwarp();
    epi_mid(acc, biasSh + 128, abase, lane);
    __syncwarp();

    // layer 3: 128 -> 256 in two 128-col chunks, fused masked max
    gemm_acc<L3_KT, 16, 32>(abase, g_B + OFF_L3, 0, lane, acc);
    epi_out(acc, biasSh + 256, vmask, out + (size_t)c * 256, lane);
    gemm_acc<L3_KT, 16, 32>(abase, g_B + OFF_L3, 16, lane, acc);
    epi_out(acc, biasSh + 384, vmask, out + (size_t)c * 256 + 128, lane);

    // tails: pos[idx] then batch[idx]
    if (lane == 0) out[(size_t)MC * 256 + (size_t)c * 3 + 0] = cpx;
    if (lane == 1) out[(size_t)MC * 256 + (size_t)c * 3 + 1] = cpy;
    if (lane == 2) out[(size_t)MC * 256 + (size_t)c * 3 + 2] = cpz;
    if (lane == 3) out[(size_t)MC * 259 + c] = (float)__ldg(batch + ci);
}

// ============================================================================
extern "C" void kernel_launch(void* const* d_in, const int* in_sizes, int n_in,
                              void* d_out, int out_size)
{
    const float* x     = (const float*)d_in[0];
    const float* pos   = (const float*)d_in[1];
    const int*   batch = (const int*)  d_in[2];
    const int*   idx   = (const int*)  d_in[3];
    const float* W1    = (const float*)d_in[4];
    const float* b1    = (const float*)d_in[5];
    const float* W2    = (const float*)d_in[6];
    const float* b2    = (const float*)d_in[7];
    const float* W3    = (const float*)d_in[8];
    const float* b3    = (const float*)d_in[9];
    float* out = (float*)d_out;

    cudaFuncSetAttribute(mlp_kernel, cudaFuncAttributeMaxDynamicSharedMemorySize, SMEM_BYTES);

    zero_w_kernel<<<64, 256>>>();
    conv_w_kernel<<<(67 * 128 + 128 * 128 + 128 * 256 + 255) / 256, 256>>>(W1, W2, W3);
    knn_kernel<<<MC, 256>>>(pos, batch, idx);
    mlp_kernel<<<MC / 4, 128, SMEM_BYTES>>>(x, pos, batch, idx, b1, b2, b3, out);
}

// round 15
// speedup vs baseline: 1.9085x; 1.1395x over previous
#include <cuda_runtime.h>
#include <cuda_fp16.h>
#include <math.h>
#include <stdint.h>

// ---------------- problem constants ----------------
#define NTOT 32768
#define NB   8
#define DIN  64
#define MC   8192
#define KN   32
#define PPC  4096
#define R2   0.04f

// ---------------- fragment-image geometry ----------------
// B images fragment-linear: tile (kt,nt) -> 32 lanes x uint2 {b0,b1}
// (PTX m16n8k16 B layout). fp16 single image; single-pass A*B.
#define L1_KT 5          // K=80 (67 padded)
#define L2_KT 8          // K=128
#define L3_KT 8          // K=128
#define OFF_L1 0
#define OFF_L2 (OFF_L1 + L1_KT * 16 * 32)
#define OFF_L3 (OFF_L2 + L2_KT * 16 * 32)
#define B_TOTAL (OFF_L3 + L3_KT * 32 * 32)   // uint2 units

// ---------------- scratch ----------------
__device__ int   g_nbr[MC * KN];
__device__ int   g_val[MC * KN];
__device__ uint2 g_B[B_TOTAL];

// A images: per warp TWO buffers of [32 rows][128 fp16 cols] = 8KB each,
// swizzled: addr(row, chunk) = bufbase + row*256 + ((chunk ^ (row&7)) * 16)
#define WARP_A_BYTES 16384                       // 2 x 8KB
#define SMEM_BYTES   (4 * WARP_A_BYTES + 512 * 4)

// ========================= helpers =========================
__device__ __forceinline__ uint32_t smem_u32(const void* p) {
    uint32_t a;
    asm("{ .reg .u64 t; cvta.to.shared.u64 t, %1; cvt.u32.u64 %0, t; }" : "=r"(a) : "l"(p));
    return a;
}
__device__ __forceinline__ void sts32(uint32_t a, uint32_t v) {
    asm volatile("st.shared.b32 [%0], %1;" :: "r"(a), "r"(v));
}
__device__ __forceinline__ void sts128(uint32_t a, uint32_t v0, uint32_t v1, uint32_t v2, uint32_t v3) {
    asm volatile("st.shared.v4.b32 [%0], {%1,%2,%3,%4};" :: "r"(a), "r"(v0), "r"(v1), "r"(v2), "r"(v3));
}
__device__ __forceinline__ void ldsm4(uint32_t* r, uint32_t addr) {
    asm volatile("ldmatrix.sync.aligned.m8n8.x4.shared.b16 {%0,%1,%2,%3}, [%4];"
                 : "=r"(r[0]), "=r"(r[1]), "=r"(r[2]), "=r"(r[3]) : "r"(addr));
}
__device__ __forceinline__ void mma_f16(float* c, const uint32_t* a, uint2 b) {
    asm volatile("mma.sync.aligned.m16n8k16.row.col.f32.f16.f16.f32 "
                 "{%0,%1,%2,%3}, {%4,%5,%6,%7}, {%8,%9}, {%0,%1,%2,%3};"
                 : "+f"(c[0]), "+f"(c[1]), "+f"(c[2]), "+f"(c[3])
                 : "r"(a[0]), "r"(a[1]), "r"(a[2]), "r"(a[3]), "r"(b.x), "r"(b.y));
}
__device__ __forceinline__ uint32_t pack_h2(float a, float b) {
    __half2 h = __floats2half2_rn(a, b);          // .x=a (low 16), .y=b (high 16)
    return *reinterpret_cast<uint32_t*>(&h);
}
__device__ __forceinline__ unsigned int fkey(float f) {
    unsigned int b = __float_as_uint(f);
    return b ^ ((b & 0x80000000u) ? 0xFFFFFFFFu : 0x80000000u);
}

// ============================================================================
// Kernel 0a: zero the fragment image (covers K-padding rows of layer 1)
// ============================================================================
__global__ void zero_w_kernel() {
    uint32_t* p = (uint32_t*)g_B;
    int n = B_TOTAL * 2;
    for (int i = blockIdx.x * blockDim.x + threadIdx.x; i < n; i += gridDim.x * blockDim.x)
        p[i] = 0;
}

// ============================================================================
// Kernel 0b: fp32 weights -> fp16 fragment-linear image
// ============================================================================
__global__ void conv_w_kernel(const float* __restrict__ W1,
                              const float* __restrict__ W2,
                              const float* __restrict__ W3) {
    int e = blockIdx.x * blockDim.x + threadIdx.x;
    int k, n, NTS; float v; unsigned baseH;
    if (e < 67 * 128) {
        k = e / 128; n = e % 128; v = W1[e]; NTS = 16;
        baseH = OFF_L1 * 4u;
    } else if (e < 67 * 128 + 128 * 128) {
        int i = e - 67 * 128; k = i / 128; n = i % 128; v = W2[i]; NTS = 16;
        baseH = OFF_L2 * 4u;
    } else if (e < 67 * 128 + 128 * 128 + 128 * 256) {
        int i = e - 67 * 128 - 128 * 128; k = i / 256; n = i % 256; v = W3[i]; NTS = 32;
        baseH = OFF_L3 * 4u;
    } else return;

    __half hb = __float2half_rn(v);

    int kt = k >> 4, kin = k & 15, nt = n >> 3, nin = n & 7;
    int lane = nin * 4 + ((kin & 7) >> 1);
    int reg  = kin >> 3;
    int half = kin & 1;
    unsigned idx = ((unsigned)(kt * NTS + nt) * 32 + lane) * 4 + reg * 2 + half;
    unsigned short* B = (unsigned short*)g_B;
    B[baseH + idx] = __half_as_ushort(hb);
}

// ============================================================================
// Kernel 1: ball-filtered exact KNN, 8 centers per block.
// Each thread register-caches its 16 candidate points (reloaded only when the
// cloud changes, i.e. at most twice per block). Per center: count -> ballot
// compaction -> parallel rank selection. Same keys/ties as before (exact).
// ============================================================================
#define CANDCAP 2048
__global__ __launch_bounds__(256) void knn_kernel(
    const float* __restrict__ pos,
    const int*   __restrict__ batch,
    const int*   __restrict__ idx)
{
    __shared__ unsigned long long cand[CANDCAP];
    __shared__ int  woff[9];
    __shared__ float scx[8], scy[8], scz[8], scc[8];
    __shared__ int   sbase[8];

    const int m0   = blockIdx.x * 8;
    const int tid  = threadIdx.x;
    const int lane = tid & 31, w = tid >> 5;

    if (tid < 8) {
        int ci = idx[m0 + tid];
        float cx = pos[3 * ci], cy = pos[3 * ci + 1], cz = pos[3 * ci + 2];
        scx[tid] = cx; scy[tid] = cy; scz[tid] = cz;
        scc[tid] = cx * cx + cy * cy + cz * cz;
        sbase[tid] = batch[ci] * PPC;
    }
    __syncthreads();

    float px[16], py[16], pz[16], pp[16];
    int curbase = -1;

    for (int cc = 0; cc < 8; cc++) {
        const int base = sbase[cc];
        if (base != curbase) {
            #pragma unroll
            for (int r = 0; r < 16; r++) {
                int j = tid + r * 256;
                const float* p = pos + 3 * (base + j);
                px[r] = p[0]; py[r] = p[1]; pz[r] = p[2];
                pp[r] = px[r] * px[r] + py[r] * py[r] + pz[r] * pz[r];
            }
            curbase = base;
        }
        const float cx = scx[cc], cy = scy[cc], cz = scz[cc], ccv = scc[cc];

        float d2[16];
        int cnt = 0;
        #pragma unroll
        for (int r = 0; r < 16; r++) {
            float dot = cx * px[r] + cy * py[r] + cz * pz[r];
            d2[r] = (ccv + pp[r]) - 2.0f * dot;
            cnt += (d2[r] <= R2) ? 1 : 0;
        }
        #pragma unroll
        for (int off = 16; off; off >>= 1) cnt += __shfl_down_sync(0xffffffffu, cnt, off);
        if (lane == 0) woff[w] = cnt;
        __syncthreads();
        if (tid == 0) {
            int acc = 0;
            #pragma unroll
            for (int t = 0; t < 8; t++) { int c = woff[t]; woff[t] = acc; acc += c; }
            woff[8] = acc;
        }
        __syncthreads();

        {
            int off = woff[w];
            #pragma unroll
            for (int r = 0; r < 16; r++) {
                int j = tid + r * 256;
                bool pred = (d2[r] <= R2);
                unsigned int mask = __ballot_sync(0xffffffffu, pred);
                if (pred) {
                    int p = off + __popc(mask & ((1u << lane) - 1u));
                    if (p < CANDCAP)
                        cand[p] = ((unsigned long long)fkey(d2[r]) << 12) | (unsigned)j;
                }
                off += __popc(mask);
            }
        }
        __syncthreads();

        const int C = min(woff[8], CANDCAP);
        const int m = m0 + cc;
        for (int s = tid; s < C; s += 256) {
            unsigned long long key = cand[s];
            int rank = 0;
            for (int t = 0; t < C; t++) rank += (cand[t] < key) ? 1 : 0;
            if (rank < KN) {
                g_nbr[m * KN + rank] = base + (int)(key & 0xFFFu);
                g_val[m * KN + rank] = 1;
            }
        }
        if (tid >= C && tid < KN) {
            g_nbr[m * KN + tid] = base;
            g_val[m * KN + tid] = 0;
        }
        __syncthreads();   // cand/woff reused by next center
    }
}

// ============================================================================
// Warp-level GEMM (single-pass fp16), NT=8 column chunk, B double-buffered:
// next k-tile's 8 B fragments are loaded while the current tile's MMAs issue.
// ============================================================================
template <int KT, int NTS>
__device__ __forceinline__ void gemm8(uint32_t abase,
                                      const uint2* __restrict__ B,
                                      int ntoff, int lane,
                                      float (&acc)[2][8][4])
{
    #pragma unroll
    for (int m = 0; m < 2; m++)
        #pragma unroll
        for (int nt = 0; nt < 8; nt++)
            #pragma unroll
            for (int q = 0; q < 4; q++) acc[m][nt][q] = 0.0f;

    const int i = lane >> 3, jj = lane & 7;
    const int cpart = i >> 1;
    const uint32_t rb0 = abase + (uint32_t)(jj + (i & 1) * 8) * 256;
    const uint32_t rb1 = rb0 + 16 * 256;

    uint2 bfr[2][8];
    {
        const uint2* bp = B + (size_t)ntoff * 32 + lane;
        #pragma unroll
        for (int nt = 0; nt < 8; nt++) bfr[0][nt] = __ldg(bp + nt * 32);
    }

    #pragma unroll
    for (int kt = 0; kt < KT; kt++) {
        if (kt + 1 < KT) {
            const uint2* bp = B + (size_t)((kt + 1) * NTS + ntoff) * 32 + lane;
            #pragma unroll
            for (int nt = 0; nt < 8; nt++) bfr[(kt + 1) & 1][nt] = __ldg(bp + nt * 32);
        }
        uint32_t ch = (uint32_t)((kt * 2 + cpart) ^ jj) << 4;
        uint32_t ah0[4], ah1[4];
        ldsm4(ah0, rb0 + ch);
        ldsm4(ah1, rb1 + ch);
        #pragma unroll
        for (int nt = 0; nt < 8; nt++) {
            mma_f16(acc[0][nt], ah0, bfr[kt & 1][nt]);
            mma_f16(acc[1][nt], ah1, bfr[kt & 1][nt]);
        }
    }
}

// mid-layer epilogue: bias + relu + fp16 -> other A buffer, chunk ntbase..+7
__device__ __forceinline__ void epi_mid8(float (&acc)[2][8][4],
                                         const float* __restrict__ bias,
                                         uint32_t bufB, int ntbase, int lane)
{
    const int grp = lane >> 2, tig = lane & 3;
    #pragma unroll
    for (int nt = 0; nt < 8; nt++) {
        float b0 = bias[nt * 8 + tig * 2];
        float b1 = bias[nt * 8 + tig * 2 + 1];
        uint32_t ch = (uint32_t)(ntbase + nt);
        #pragma unroll
        for (int m = 0; m < 2; m++) {
            int row0 = m * 16 + grp, row1 = row0 + 8;
            float v0 = fmaxf(acc[m][nt][0] + b0, 0.0f);
            float v1 = fmaxf(acc[m][nt][1] + b1, 0.0f);
            float v2 = fmaxf(acc[m][nt][2] + b0, 0.0f);
            float v3 = fmaxf(acc[m][nt][3] + b1, 0.0f);
            sts32(bufB + (uint32_t)row0 * 256 + ((ch ^ (uint32_t)(row0 & 7)) << 4) + tig * 4,
                  pack_h2(v0, v1));
            sts32(bufB + (uint32_t)row1 * 256 + ((ch ^ (uint32_t)(row1 & 7)) << 4) + tig * 4,
                  pack_h2(v2, v3));
        }
    }
}

// final epilogue: bias + relu + masked max over 32 edges, write 64 cols
__device__ __forceinline__ void epi_out8(float (&acc)[2][8][4],
                                         const float* __restrict__ bias,
                                         unsigned vmask, float* __restrict__ outp,
                                         int lane)
{
    const int grp = lane >> 2, tig = lane & 3;
    #pragma unroll
    for (int nt = 0; nt < 8; nt++) {
        float b0 = bias[nt * 8 + tig * 2];
        float b1 = bias[nt * 8 + tig * 2 + 1];
        float p0 = 0.0f, p1 = 0.0f;
        #pragma unroll
        for (int m = 0; m < 2; m++) {
            int r0 = m * 16 + grp, r1 = r0 + 8;
            bool k0 = (vmask >> r0) & 1, k1 = (vmask >> r1) & 1;
            float v0 = k0 ? fmaxf(acc[m][nt][0] + b0, 0.0f) : 0.0f;
            float v1 = k0 ? fmaxf(acc[m][nt][1] + b1, 0.0f) : 0.0f;
            float v2 = k1 ? fmaxf(acc[m][nt][2] + b0, 0.0f) : 0.0f;
            float v3 = k1 ? fmaxf(acc[m][nt][3] + b1, 0.0f) : 0.0f;
            p0 = fmaxf(p0, fmaxf(v0, v2));
            p1 = fmaxf(p1, fmaxf(v1, v3));
        }
        #pragma unroll
        for (int off = 4; off <= 16; off <<= 1) {
            p0 = fmaxf(p0, __shfl_xor_sync(0xffffffffu, p0, off));
            p1 = fmaxf(p1, __shfl_xor_sync(0xffffffffu, p1, off));
        }
        if (grp == 0)
            *(float2*)(outp + nt * 8 + tig * 2) = make_float2(p0, p1);
    }
}

// ============================================================================
// Kernel 2: warp-per-center fused MLP, single-pass fp16, double-buffered A,
// 3 CTAs/SM (12 warps).
// ============================================================================
__global__ __launch_bounds__(128, 3) void mlp_kernel(
    const float* __restrict__ x,   const float* __restrict__ pos,
    const int*   __restrict__ batch, const int* __restrict__ idx,
    const float* __restrict__ b1, const float* __restrict__ b2,
    const float* __restrict__ b3, float* __restrict__ out)
{
    extern __shared__ __align__(16) unsigned char smem[];
    float* biasSh = (float*)(smem + 4 * WARP_A_BYTES);

    const int tid = threadIdx.x;
    const int lane = tid & 31, w = tid >> 5;
    const int c = blockIdx.x * 4 + w;

    for (int i = tid; i < 512; i += 128) {
        float bv = (i < 128) ? __ldg(b1 + i) : (i < 256) ? __ldg(b2 + i - 128) : __ldg(b3 + i - 256);
        biasSh[i] = bv;
    }
    __syncthreads();

    const uint32_t buf0 = smem_u32(smem) + (uint32_t)w * WARP_A_BYTES;
    const uint32_t buf1 = buf0 + 8192;

    // ---- per-lane edge
    const int nb  = __ldg((const int*)g_nbr + c * KN + lane);
    const int vld = __ldg((const int*)g_val + c * KN + lane);
    const int ci  = __ldg(idx + c);
    const float cpx = __ldg(pos + 3 * ci), cpy = __ldg(pos + 3 * ci + 1), cpz = __ldg(pos + 3 * ci + 2);
    const unsigned vmask = __ballot_sync(0xffffffffu, vld);

    // ---- gather row = lane into buf0 (fp16, chunks 0..9; 10..15 unused)
    {
        const uint32_t rowbase = buf0 + (uint32_t)lane * 256;
        const uint32_t r7 = (uint32_t)(lane & 7);
        const float4* xr = (const float4*)(x + (size_t)nb * DIN);
        #pragma unroll
        for (int q = 0; q < 16; q++) {
            float4 v = __ldg(xr + q);
            uint32_t addr = rowbase + (((uint32_t)(q >> 1) ^ r7) << 4) + ((uint32_t)(q & 1) << 3);
            sts32(addr,     pack_h2(v.x, v.y));
            sts32(addr + 4, pack_h2(v.z, v.w));
        }
        float rx = __ldg(pos + 3 * nb)     - cpx;
        float ry = __ldg(pos + 3 * nb + 1) - cpy;
        float rz = __ldg(pos + 3 * nb + 2) - cpz;
        sts128(rowbase + ((8u ^ r7) << 4), pack_h2(rx, ry), pack_h2(rz, 0.0f), 0u, 0u);
        sts128(rowbase + ((9u ^ r7) << 4), 0u, 0u, 0u, 0u);
    }
    __syncwarp();

    float acc[2][8][4];

    // layer 1: K=80 -> 128, buf0 -> buf1
    #pragma unroll
    for (int ntc = 0; ntc < 2; ntc++) {
        gemm8<L1_KT, 16>(buf0, g_B + OFF_L1, ntc * 8, lane, acc);
        epi_mid8(acc, biasSh + ntc * 64, buf1, ntc * 8, lane);
    }
    __syncwarp();

    // layer 2: 128 -> 128, buf1 -> buf0
    #pragma unroll
    for (int ntc = 0; ntc < 2; ntc++) {
        gemm8<L2_KT, 16>(buf1, g_B + OFF_L2, ntc * 8, lane, acc);
        epi_mid8(acc, biasSh + 128 + ntc * 64, buf0, ntc * 8, lane);
    }
    __syncwarp();

    // layer 3: 128 -> 256, buf0 -> out (4 chunks of 64 cols), fused masked max
    #pragma unroll
    for (int ntc = 0; ntc < 4; ntc++) {
        gemm8<L3_KT, 32>(buf0, g_B + OFF_L3, ntc * 8, lane, acc);
        epi_out8(acc, biasSh + 256 + ntc * 64, vmask, out + (size_t)c * 256 + ntc * 64, lane);
    }

    // tails: pos[idx] then batch[idx]
    if (lane == 0) out[(size_t)MC * 256 + (size_t)c * 3 + 0] = cpx;
    if (lane == 1) out[(size_t)MC * 256 + (size_t)c * 3 + 1] = cpy;
    if (lane == 2) out[(size_t)MC * 256 + (size_t)c * 3 + 2] = cpz;
    if (lane == 3) out[(size_t)MC * 259 + c] = (float)__ldg(batch + ci);
}

// ============================================================================
extern "C" void kernel_launch(void* const* d_in, const int* in_sizes, int n_in,
                              void* d_out, int out_size)
{
    const float* x     = (const float*)d_in[0];
    const float* pos   = (const float*)d_in[1];
    const int*   batch = (const int*)  d_in[2];
    const int*   idx   = (const int*)  d_in[3];
    const float* W1    = (const float*)d_in[4];
    const float* b1    = (const float*)d_in[5];
    const float* W2    = (const float*)d_in[6];
    const float* b2    = (const float*)d_in[7];
    const float* W3    = (const float*)d_in[8];
    const float* b3    = (const float*)d_in[9];
    float* out = (float*)d_out;

    cudaFuncSetAttribute(mlp_kernel, cudaFuncAttributeMaxDynamicSharedMemorySize, SMEM_BYTES);

    zero_w_kernel<<<64, 256>>>();
    conv_w_kernel<<<(67 * 128 + 128 * 128 + 128 * 256 + 255) / 256, 256>>>(W1, W2, W3);
    knn_kernel<<<MC / 8, 256>>>(pos, batch, idx);
    mlp_kernel<<<MC / 4, 128, SMEM_BYTES>>>(x, pos, batch, idx, b1, b2, b3, out);
}